// round 1
// baseline (speedup 1.0000x reference)
#include <cuda_runtime.h>
#include <cuda_bf16.h>

// Problem constants (fixed by the dataset)
#define SDIM 2048   // tokens per group
#define MDIM 768    // hidden
#define HDIM 3072   // intermediate
#define NEXP 16     // experts
#define CAP  256    // capacity = 2*S/E
#define GMAX 2      // groups (4*1024 tokens / 2048)

// ---------------- scratch (device globals; no runtime allocation) -----------
__device__ float g_disp[NEXP * GMAX * CAP * MDIM];   // [E][G][C][M]  ~25 MB
__device__ float g_h   [NEXP * GMAX * CAP * HDIM];   // [E][G][C][H]  ~100 MB
__device__ float g_eo  [NEXP * GMAX * CAP * MDIM];   // [E][G][C][M]  ~25 MB
__device__ int   g_e1  [GMAX * SDIM];
__device__ int   g_e2  [GMAX * SDIM];
__device__ int   g_pos1[GMAX * SDIM];                // -1 => dropped
__device__ int   g_pos2[GMAX * SDIM];
__device__ float g_gv1 [GMAX * SDIM];                // raw softmax top-1 prob
__device__ float g_gv2 [GMAX * SDIM];
__device__ float g_w1  [GMAX * SDIM];                // normalized combine weights
__device__ float g_w2  [GMAX * SDIM];

// ---------------- 1) gating: softmax(x @ wg), top-2 -------------------------
// one warp per token
__global__ void gating_kernel(const float* __restrict__ x,
                              const float* __restrict__ wg, int T) {
    int warp = (blockIdx.x * blockDim.x + threadIdx.x) >> 5;
    int lane = threadIdx.x & 31;
    if (warp >= T) return;
    const float* xr = x + (size_t)warp * MDIM;
    float acc[NEXP];
#pragma unroll
    for (int e = 0; e < NEXP; e++) acc[e] = 0.f;
    for (int k = lane; k < MDIM; k += 32) {
        float xv = xr[k];
        const float* w = wg + k * NEXP;
#pragma unroll
        for (int e = 0; e < NEXP; e++) acc[e] += xv * w[e];
    }
#pragma unroll
    for (int e = 0; e < NEXP; e++) {
#pragma unroll
        for (int off = 16; off; off >>= 1)
            acc[e] += __shfl_xor_sync(0xffffffffu, acc[e], off);
    }
    if (lane == 0) {
        float mx = acc[0];
#pragma unroll
        for (int e = 1; e < NEXP; e++) mx = fmaxf(mx, acc[e]);
        float p[NEXP], sum = 0.f;
#pragma unroll
        for (int e = 0; e < NEXP; e++) { p[e] = expf(acc[e] - mx); sum += p[e]; }
        float inv = 1.f / sum;
        // top-1 (first-index tie-break, matches jnp.argmax)
        int e1 = 0; float b1 = p[0];
#pragma unroll
        for (int e = 1; e < NEXP; e++) if (p[e] > b1) { b1 = p[e]; e1 = e; }
        // top-2 = argmax excluding e1
        int e2 = 0; float b2 = -1.f;
#pragma unroll
        for (int e = 0; e < NEXP; e++)
            if (e != e1 && p[e] > b2) { b2 = p[e]; e2 = e; }
        g_e1[warp] = e1; g_e2[warp] = e2;
        g_gv1[warp] = b1 * inv; g_gv2[warp] = b2 * inv;
    }
}

// ---------------- 2) capacity scan per group --------------------------------
// one block per group; threads 0..15 each own one expert and scan the 2048
// tokens sequentially (reproduces jnp.cumsum position semantics exactly).
__global__ void scan_kernel(int G) {
    int g = blockIdx.x;
    int tid = threadIdx.x;
    __shared__ int s_cnt1[NEXP];
    int base = g * SDIM;
    if (tid < NEXP) {
        int cnt = 0;
        for (int s = 0; s < SDIM; s++) {
            if (g_e1[base + s] == tid) {
                int p = cnt++;
                g_pos1[base + s] = (p < CAP) ? p : -1;
            }
        }
        s_cnt1[tid] = cnt < CAP ? cnt : CAP;   // mask_1_count (capacity-clipped)
    }
    __syncthreads();
    if (tid < NEXP) {
        int cnt = 0, off = s_cnt1[tid];
        for (int s = 0; s < SDIM; s++) {
            if (g_e2[base + s] == tid) {
                int p = cnt++ + off;           // cumsum(mask_2) + mask_1_count
                g_pos2[base + s] = (p < CAP) ? p : -1;
            }
        }
    }
    __syncthreads();
    for (int s = tid; s < SDIM; s += blockDim.x) {
        int t = base + s;
        float a = (g_pos1[t] >= 0) ? g_gv1[t] : 0.f;
        float b = (g_pos2[t] >= 0) ? g_gv2[t] : 0.f;
        float den = a + b;
        den = (den > 0.f) ? den : 1.f;
        g_w1[t] = a / den;
        g_w2[t] = b / den;
    }
}

// ---------------- 3) scatter tokens into dispatch buffer --------------------
__global__ void scatter_kernel(const float* __restrict__ x, int G) {
    int t = blockIdx.x;
    int g = t / SDIM;
    const float* xr = x + (size_t)t * MDIM;
    int p1 = g_pos1[t], p2 = g_pos2[t];
    float* d1 = (p1 >= 0) ? g_disp + (((size_t)g_e1[t] * G + g) * CAP + p1) * MDIM : nullptr;
    float* d2 = (p2 >= 0) ? g_disp + (((size_t)g_e2[t] * G + g) * CAP + p2) * MDIM : nullptr;
    for (int m = threadIdx.x; m < MDIM; m += blockDim.x) {
        float v = xr[m];
        if (d1) d1[m] = v;
        if (d2) d2[m] = v;
    }
}

// ---------------- 4/5) batched SGEMM: 128x128 tile, 8x8 microtile -----------
template<bool RELU>
__device__ __forceinline__ void sgemm_body(
    const float* __restrict__ A, const float* __restrict__ B, float* __restrict__ C,
    int K, int lda, int ldb, int ldc) {
    __shared__ float As[8][128];
    __shared__ float Bs[8][128];
    const int tid = threadIdx.x;
    const int arow = tid >> 1, acol = (tid & 1) * 4;   // A tile loader: 128x8
    const int brow = tid >> 5, bcol = (tid & 31) * 4;  // B tile loader: 8x128
    const int tx = tid & 15, ty = tid >> 4;            // 16x16 threads, 8x8 each

    A += (size_t)blockIdx.y * 128 * lda;
    B += (size_t)blockIdx.x * 128;
    C += (size_t)blockIdx.y * 128 * ldc + (size_t)blockIdx.x * 128;

    float acc[8][8];
#pragma unroll
    for (int i = 0; i < 8; i++)
#pragma unroll
        for (int j = 0; j < 8; j++) acc[i][j] = 0.f;

    for (int k0 = 0; k0 < K; k0 += 8) {
        float4 a4 = *(const float4*)(A + (size_t)arow * lda + k0 + acol);
        As[acol + 0][arow] = a4.x;
        As[acol + 1][arow] = a4.y;
        As[acol + 2][arow] = a4.z;
        As[acol + 3][arow] = a4.w;
        *(float4*)&Bs[brow][bcol] = *(const float4*)(B + (size_t)(k0 + brow) * ldb + bcol);
        __syncthreads();
#pragma unroll
        for (int k = 0; k < 8; k++) {
            float ar[8], br[8];
            *(float4*)&ar[0] = *(const float4*)&As[k][ty * 8];
            *(float4*)&ar[4] = *(const float4*)&As[k][ty * 8 + 4];
            *(float4*)&br[0] = *(const float4*)&Bs[k][tx * 8];
            *(float4*)&br[4] = *(const float4*)&Bs[k][tx * 8 + 4];
#pragma unroll
            for (int i = 0; i < 8; i++)
#pragma unroll
                for (int j = 0; j < 8; j++) acc[i][j] += ar[i] * br[j];
        }
        __syncthreads();
    }
#pragma unroll
    for (int i = 0; i < 8; i++) {
        float* cr = C + (size_t)(ty * 8 + i) * ldc + tx * 8;
#pragma unroll
        for (int j = 0; j < 8; j++) {
            float v = acc[i][j];
            if (RELU) v = fmaxf(v, 0.f);
            cr[j] = v;
        }
    }
}

// GEMM1: h[e] = relu(disp[e] @ wi[e]),  [G*C,768] @ [768,3072]
__global__ __launch_bounds__(256) void gemm1_kernel(const float* __restrict__ wi, int G) {
    int e = blockIdx.z;
    const float* A = g_disp + (size_t)e * G * CAP * MDIM;
    const float* B = wi + (size_t)e * MDIM * HDIM;
    float* C = g_h + (size_t)e * G * CAP * HDIM;
    sgemm_body<true>(A, B, C, MDIM, MDIM, HDIM, HDIM);
}

// GEMM2: eo[e] = h[e] @ wo[e],  [G*C,3072] @ [3072,768]
__global__ __launch_bounds__(256) void gemm2_kernel(const float* __restrict__ wo, int G) {
    int e = blockIdx.z;
    const float* A = g_h + (size_t)e * G * CAP * HDIM;
    const float* B = wo + (size_t)e * HDIM * MDIM;
    float* C = g_eo + (size_t)e * G * CAP * MDIM;
    sgemm_body<false>(A, B, C, HDIM, HDIM, MDIM, MDIM);
}

// ---------------- 6) combine ------------------------------------------------
__global__ void combine_kernel(float* __restrict__ out, int G) {
    int t = blockIdx.x;
    int g = t / SDIM;
    int p1 = g_pos1[t], p2 = g_pos2[t];
    float w1 = g_w1[t], w2 = g_w2[t];
    const float* r1 = (p1 >= 0) ? g_eo + (((size_t)g_e1[t] * G + g) * CAP + p1) * MDIM : nullptr;
    const float* r2 = (p2 >= 0) ? g_eo + (((size_t)g_e2[t] * G + g) * CAP + p2) * MDIM : nullptr;
    float* o = out + (size_t)t * MDIM;
    for (int m = threadIdx.x; m < MDIM; m += blockDim.x) {
        float v = 0.f;
        if (r1) v += w1 * r1[m];
        if (r2) v += w2 * r2[m];
        o[m] = v;
    }
}

// ---------------- launcher --------------------------------------------------
extern "C" void kernel_launch(void* const* d_in, const int* in_sizes, int n_in,
                              void* d_out, int out_size) {
    const float* x  = (const float*)d_in[0];   // [4,1024,768] fp32
    const float* wg = (const float*)d_in[1];   // [768,16]
    const float* wi = (const float*)d_in[2];   // [16,768,3072]
    const float* wo = (const float*)d_in[3];   // [16,3072,768]
    float* out = (float*)d_out;

    int T = in_sizes[0] / MDIM;   // 4096 tokens
    int G = T / SDIM;             // 2 groups
    if (G > GMAX) G = GMAX;       // static buffers sized for the dataset shape
    int Mr = G * CAP;             // 512 rows per expert

    gating_kernel<<<(T + 3) / 4, 128>>>(x, wg, T);
    scan_kernel<<<G, 256>>>(G);
    scatter_kernel<<<T, 256>>>(x, G);
    gemm1_kernel<<<dim3(HDIM / 128, Mr / 128, NEXP), 256>>>(wi, G);
    gemm2_kernel<<<dim3(MDIM / 128, Mr / 128, NEXP), 256>>>(wo, G);
    combine_kernel<<<T, 256>>>(out, G);
}

// round 7
// speedup vs baseline: 1.1209x; 1.1209x over previous
#include <cuda_runtime.h>
#include <cuda_bf16.h>

// Problem constants (fixed by the dataset)
#define SDIM 2048   // tokens per group
#define MDIM 768    // hidden size
#define HDIM 3072   // intermediate size
#define NEXP 16     // num experts
#define CAP  256    // capacity = 2*S/E
#define GMAX 2      // groups (4*1024 tokens / 2048)

// ---------------- scratch (device globals; no runtime allocation) -----------
__device__ __align__(128) float g_disp[NEXP * GMAX * CAP * MDIM];   // [E][G][C][M]
__device__ __align__(128) float g_h   [NEXP * GMAX * CAP * HDIM];   // [E][G][C][H]
__device__ __align__(128) float g_eo  [NEXP * GMAX * CAP * MDIM];   // [E][G][C][M]
__device__ int   g_e1  [GMAX * SDIM];
__device__ int   g_e2  [GMAX * SDIM];
__device__ int   g_pos1[GMAX * SDIM];                // -1 => dropped
__device__ int   g_pos2[GMAX * SDIM];
__device__ float g_gv1 [GMAX * SDIM];
__device__ float g_gv2 [GMAX * SDIM];
__device__ float g_w1  [GMAX * SDIM];
__device__ float g_w2  [GMAX * SDIM];

// ---------------- 1) gating: softmax(x @ wg), top-2 -------------------------
__global__ void gating_kernel(const float* __restrict__ x,
                              const float* __restrict__ wg, int T) {
    int warp = (blockIdx.x * blockDim.x + threadIdx.x) >> 5;
    int lane = threadIdx.x & 31;
    if (warp >= T) return;
    const float* xr = x + (size_t)warp * MDIM;
    float acc[NEXP];
#pragma unroll
    for (int e = 0; e < NEXP; e++) acc[e] = 0.f;
    for (int k = lane; k < MDIM; k += 32) {
        float xv = xr[k];
        const float* w = wg + k * NEXP;
#pragma unroll
        for (int e = 0; e < NEXP; e++) acc[e] += xv * w[e];
    }
#pragma unroll
    for (int e = 0; e < NEXP; e++) {
#pragma unroll
        for (int off = 16; off; off >>= 1)
            acc[e] += __shfl_xor_sync(0xffffffffu, acc[e], off);
    }
    if (lane == 0) {
        float mx = acc[0];
#pragma unroll
        for (int e = 1; e < NEXP; e++) mx = fmaxf(mx, acc[e]);
        float p[NEXP], sum = 0.f;
#pragma unroll
        for (int e = 0; e < NEXP; e++) { p[e] = expf(acc[e] - mx); sum += p[e]; }
        float inv = 1.f / sum;
        int e1 = 0; float b1 = p[0];
#pragma unroll
        for (int e = 1; e < NEXP; e++) if (p[e] > b1) { b1 = p[e]; e1 = e; }
        int e2 = 0; float b2 = -1.f;
#pragma unroll
        for (int e = 0; e < NEXP; e++)
            if (e != e1 && p[e] > b2) { b2 = p[e]; e2 = e; }
        g_e1[warp] = e1; g_e2[warp] = e2;
        g_gv1[warp] = b1 * inv; g_gv2[warp] = b2 * inv;
    }
}

// ---------------- 2) capacity scan per group (R1-proven) ---------------------
__global__ void scan_kernel(int G) {
    int g = blockIdx.x;
    int tid = threadIdx.x;
    __shared__ int s_cnt1[NEXP];
    int base = g * SDIM;
    if (tid < NEXP) {
        int cnt = 0;
        for (int s = 0; s < SDIM; s++) {
            if (g_e1[base + s] == tid) {
                int p = cnt++;
                g_pos1[base + s] = (p < CAP) ? p : -1;
            }
        }
        s_cnt1[tid] = cnt < CAP ? cnt : CAP;
    }
    __syncthreads();
    if (tid < NEXP) {
        int cnt = 0, off = s_cnt1[tid];
        for (int s = 0; s < SDIM; s++) {
            if (g_e2[base + s] == tid) {
                int p = cnt++ + off;
                g_pos2[base + s] = (p < CAP) ? p : -1;
            }
        }
    }
    __syncthreads();
    for (int s = tid; s < SDIM; s += blockDim.x) {
        int t = base + s;
        float a = (g_pos1[t] >= 0) ? g_gv1[t] : 0.f;
        float b = (g_pos2[t] >= 0) ? g_gv2[t] : 0.f;
        float den = a + b;
        den = (den > 0.f) ? den : 1.f;
        g_w1[t] = a / den;
        g_w2[t] = b / den;
    }
}

// ---------------- 3) scatter tokens into dispatch buffer --------------------
__global__ void scatter_kernel(const float* __restrict__ x, int G) {
    int t = blockIdx.x;
    int g = t / SDIM;
    const float* xr = x + (size_t)t * MDIM;
    int p1 = g_pos1[t], p2 = g_pos2[t];
    float* d1 = (p1 >= 0) ? g_disp + (((size_t)g_e1[t] * G + g) * CAP + p1) * MDIM : nullptr;
    float* d2 = (p2 >= 0) ? g_disp + (((size_t)g_e2[t] * G + g) * CAP + p2) * MDIM : nullptr;
    for (int m = threadIdx.x; m < MDIM; m += blockDim.x) {
        float v = xr[m];
        if (d1) d1[m] = v;
        if (d2) d2[m] = v;
    }
}

// ---------------- 4/5) SGEMM: 128x128 tile, split 8x8 microtile --------------
// Conflict-free fragment loads: per-thread 2x2 blocks of 4x4 at
// rows {ty*4, 64+ty*4}, cols {tx*4, 64+tx*4}.
template<bool RELU>
__device__ __forceinline__ void sgemm_body(
    const float* __restrict__ A, const float* __restrict__ B, float* __restrict__ C,
    int K, int lda, int ldb, int ldc) {
    __shared__ float As[8][128];
    __shared__ float Bs[8][128];
    const int tid = threadIdx.x;
    const int arow = tid >> 1, acol = (tid & 1) * 4;   // A tile loader: 128x8
    const int brow = tid >> 5, bcol = (tid & 31) * 4;  // B tile loader: 8x128
    const int tx = tid & 15, ty = tid >> 4;            // 16x16 threads

    A += (size_t)blockIdx.y * 128 * lda;
    B += (size_t)blockIdx.x * 128;
    C += (size_t)blockIdx.y * 128 * ldc + (size_t)blockIdx.x * 128;

    float acc[8][8];
#pragma unroll
    for (int i = 0; i < 8; i++)
#pragma unroll
        for (int j = 0; j < 8; j++) acc[i][j] = 0.f;

    for (int k0 = 0; k0 < K; k0 += 8) {
        float4 a4 = *(const float4*)(A + (size_t)arow * lda + k0 + acol);
        As[acol + 0][arow] = a4.x;
        As[acol + 1][arow] = a4.y;
        As[acol + 2][arow] = a4.z;
        As[acol + 3][arow] = a4.w;
        *(float4*)&Bs[brow][bcol] = *(const float4*)(B + (size_t)(k0 + brow) * ldb + bcol);
        __syncthreads();
#pragma unroll
        for (int k = 0; k < 8; k++) {
            float ar[8], br[8];
            // A fragments: warp-broadcast (2 distinct addresses per warp)
            *(float4*)&ar[0] = *(const float4*)&As[k][ty * 4];
            *(float4*)&ar[4] = *(const float4*)&As[k][64 + ty * 4];
            // B fragments: 16 x 16B contiguous = crossbar floor, no conflicts
            *(float4*)&br[0] = *(const float4*)&Bs[k][tx * 4];
            *(float4*)&br[4] = *(const float4*)&Bs[k][64 + tx * 4];
#pragma unroll
            for (int i = 0; i < 8; i++)
#pragma unroll
                for (int j = 0; j < 8; j++) acc[i][j] += ar[i] * br[j];
        }
        __syncthreads();
    }
    // epilogue: rows ty*4+i (+64), col groups tx*4 (+64); float4 stores
#pragma unroll
    for (int ih = 0; ih < 2; ih++) {
#pragma unroll
        for (int i = 0; i < 4; i++) {
            int row = ih * 64 + ty * 4 + i;
            float* cr = C + (size_t)row * ldc;
#pragma unroll
            for (int jh = 0; jh < 2; jh++) {
                float4 v;
                v.x = acc[ih * 4 + i][jh * 4 + 0];
                v.y = acc[ih * 4 + i][jh * 4 + 1];
                v.z = acc[ih * 4 + i][jh * 4 + 2];
                v.w = acc[ih * 4 + i][jh * 4 + 3];
                if (RELU) {
                    v.x = fmaxf(v.x, 0.f); v.y = fmaxf(v.y, 0.f);
                    v.z = fmaxf(v.z, 0.f); v.w = fmaxf(v.w, 0.f);
                }
                *(float4*)(cr + jh * 64 + tx * 4) = v;
            }
        }
    }
}

// GEMM1: h[e] = relu(disp[e] @ wi[e]),  [G*C,768] @ [768,3072]
__global__ __launch_bounds__(256) void gemm1_kernel(const float* __restrict__ wi, int G) {
    int e = blockIdx.z;
    const float* A = g_disp + (size_t)e * G * CAP * MDIM;
    const float* B = wi + (size_t)e * MDIM * HDIM;
    float* C = g_h + (size_t)e * G * CAP * HDIM;
    sgemm_body<true>(A, B, C, MDIM, MDIM, HDIM, HDIM);
}

// GEMM2: eo[e] = h[e] @ wo[e],  [G*C,3072] @ [3072,768]
__global__ __launch_bounds__(256) void gemm2_kernel(const float* __restrict__ wo, int G) {
    int e = blockIdx.z;
    const float* A = g_h + (size_t)e * G * CAP * HDIM;
    const float* B = wo + (size_t)e * HDIM * MDIM;
    float* C = g_eo + (size_t)e * G * CAP * MDIM;
    sgemm_body<false>(A, B, C, HDIM, HDIM, MDIM, MDIM);
}

// ---------------- 6) combine ------------------------------------------------
__global__ void combine_kernel(float* __restrict__ out, int G) {
    int t = blockIdx.x;
    int g = t / SDIM;
    int p1 = g_pos1[t], p2 = g_pos2[t];
    float w1 = g_w1[t], w2 = g_w2[t];
    const float* r1 = (p1 >= 0) ? g_eo + (((size_t)g_e1[t] * G + g) * CAP + p1) * MDIM : nullptr;
    const float* r2 = (p2 >= 0) ? g_eo + (((size_t)g_e2[t] * G + g) * CAP + p2) * MDIM : nullptr;
    float* o = out + (size_t)t * MDIM;
    for (int m = threadIdx.x; m < MDIM; m += blockDim.x) {
        float v = 0.f;
        if (r1) v += w1 * r1[m];
        if (r2) v += w2 * r2[m];
        o[m] = v;
    }
}

// ---------------- launcher --------------------------------------------------
extern "C" void kernel_launch(void* const* d_in, const int* in_sizes, int n_in,
                              void* d_out, int out_size) {
    const float* x  = (const float*)d_in[0];   // [4,1024,768] fp32
    const float* wg = (const float*)d_in[1];   // [768,16]
    const float* wi = (const float*)d_in[2];   // [16,768,3072]
    const float* wo = (const float*)d_in[3];   // [16,3072,768]
    float* out = (float*)d_out;

    int T = in_sizes[0] / MDIM;   // 4096 tokens
    int G = T / SDIM;             // 2 groups
    if (G > GMAX) G = GMAX;
    int Mr = G * CAP;             // 512 rows per expert

    gating_kernel<<<(T + 3) / 4, 128>>>(x, wg, T);
    scan_kernel<<<G, 256>>>(G);
    scatter_kernel<<<T, 256>>>(x, G);
    gemm1_kernel<<<dim3(HDIM / 128, Mr / 128, NEXP), 256>>>(wi, G);
    gemm2_kernel<<<dim3(MDIM / 128, Mr / 128, NEXP), 256>>>(wo, G);
    combine_kernel<<<T, 256>>>(out, G);
}

// round 8
// speedup vs baseline: 1.2474x; 1.1129x over previous
#include <cuda_runtime.h>
#include <cuda_bf16.h>

// Problem constants (fixed by the dataset)
#define SDIM 2048   // tokens per group
#define MDIM 768    // hidden size
#define HDIM 3072   // intermediate size
#define NEXP 16     // num experts
#define CAP  256    // capacity = 2*S/E
#define GMAX 2      // groups (4*1024 tokens / 2048)

// ---------------- scratch (device globals; no runtime allocation) -----------
__device__ __align__(128) float g_disp[NEXP * GMAX * CAP * MDIM];   // [E][G][C][M]
__device__ __align__(128) float g_h   [NEXP * GMAX * CAP * HDIM];   // [E][G][C][H]
__device__ __align__(128) float g_eo  [NEXP * GMAX * CAP * MDIM];   // [E][G][C][M]
__device__ int   g_e1  [GMAX * SDIM];
__device__ int   g_e2  [GMAX * SDIM];
__device__ int   g_pos1[GMAX * SDIM];                // -1 => dropped
__device__ int   g_pos2[GMAX * SDIM];
__device__ float g_gv1 [GMAX * SDIM];
__device__ float g_gv2 [GMAX * SDIM];
__device__ float g_w1  [GMAX * SDIM];
__device__ float g_w2  [GMAX * SDIM];

// ---------------- 1) gating: softmax(x @ wg), top-2 -------------------------
__global__ void gating_kernel(const float* __restrict__ x,
                              const float* __restrict__ wg, int T) {
    int warp = (blockIdx.x * blockDim.x + threadIdx.x) >> 5;
    int lane = threadIdx.x & 31;
    if (warp >= T) return;
    const float* xr = x + (size_t)warp * MDIM;
    float acc[NEXP];
#pragma unroll
    for (int e = 0; e < NEXP; e++) acc[e] = 0.f;
    for (int k = lane; k < MDIM; k += 32) {
        float xv = xr[k];
        const float* w = wg + k * NEXP;
#pragma unroll
        for (int e = 0; e < NEXP; e++) acc[e] += xv * w[e];
    }
#pragma unroll
    for (int e = 0; e < NEXP; e++) {
#pragma unroll
        for (int off = 16; off; off >>= 1)
            acc[e] += __shfl_xor_sync(0xffffffffu, acc[e], off);
    }
    if (lane == 0) {
        float mx = acc[0];
#pragma unroll
        for (int e = 1; e < NEXP; e++) mx = fmaxf(mx, acc[e]);
        float p[NEXP], sum = 0.f;
#pragma unroll
        for (int e = 0; e < NEXP; e++) { p[e] = expf(acc[e] - mx); sum += p[e]; }
        float inv = 1.f / sum;
        int e1 = 0; float b1 = p[0];
#pragma unroll
        for (int e = 1; e < NEXP; e++) if (p[e] > b1) { b1 = p[e]; e1 = e; }
        int e2 = 0; float b2 = -1.f;
#pragma unroll
        for (int e = 0; e < NEXP; e++)
            if (e != e1 && p[e] > b2) { b2 = p[e]; e2 = e; }
        g_e1[warp] = e1; g_e2[warp] = e2;
        g_gv1[warp] = b1 * inv; g_gv2[warp] = b2 * inv;
    }
}

// ---------------- 2) capacity scan per group --------------------------------
__global__ void scan_kernel(int G) {
    int g = blockIdx.x;
    int tid = threadIdx.x;
    __shared__ int s_cnt1[NEXP];
    int base = g * SDIM;
    if (tid < NEXP) {
        int cnt = 0;
        for (int s = 0; s < SDIM; s++) {
            if (g_e1[base + s] == tid) {
                int p = cnt++;
                g_pos1[base + s] = (p < CAP) ? p : -1;
            }
        }
        s_cnt1[tid] = cnt < CAP ? cnt : CAP;
    }
    __syncthreads();
    if (tid < NEXP) {
        int cnt = 0, off = s_cnt1[tid];
        for (int s = 0; s < SDIM; s++) {
            if (g_e2[base + s] == tid) {
                int p = cnt++ + off;
                g_pos2[base + s] = (p < CAP) ? p : -1;
            }
        }
    }
    __syncthreads();
    for (int s = tid; s < SDIM; s += blockDim.x) {
        int t = base + s;
        float a = (g_pos1[t] >= 0) ? g_gv1[t] : 0.f;
        float b = (g_pos2[t] >= 0) ? g_gv2[t] : 0.f;
        float den = a + b;
        den = (den > 0.f) ? den : 1.f;
        g_w1[t] = a / den;
        g_w2[t] = b / den;
    }
}

// ---------------- 3) scatter tokens into dispatch buffer --------------------
__global__ void scatter_kernel(const float* __restrict__ x, int G) {
    int t = blockIdx.x;
    int g = t / SDIM;
    const float* xr = x + (size_t)t * MDIM;
    int p1 = g_pos1[t], p2 = g_pos2[t];
    float* d1 = (p1 >= 0) ? g_disp + (((size_t)g_e1[t] * G + g) * CAP + p1) * MDIM : nullptr;
    float* d2 = (p2 >= 0) ? g_disp + (((size_t)g_e2[t] * G + g) * CAP + p2) * MDIM : nullptr;
    for (int m = threadIdx.x; m < MDIM; m += blockDim.x) {
        float v = xr[m];
        if (d1) d1[m] = v;
        if (d2) d2[m] = v;
    }
}

// ---------------- 4/5) SGEMM: 128x128 tile, K-chunk 16, double-buffered ------
// One __syncthreads per chunk; global loads for chunk t+1 issued before the
// compute of chunk t (latency hidden under 1024 FFMAs), STS into idle stage.
// Conflict-free fragments: A broadcast rows {ty*4, 64+ty*4}, B contiguous
// col groups {tx*4, 64+tx*4}.
template<bool RELU>
__device__ __forceinline__ void sgemm_body(
    const float* __restrict__ A, const float* __restrict__ B, float* __restrict__ C,
    int K, int lda, int ldb, int ldc) {
    __shared__ float As[2][16][128];
    __shared__ float Bs[2][16][128];
    const int tid = threadIdx.x;
    const int arow = tid >> 1, acol = (tid & 1) * 8;   // A loader: 128 rows x 16 k
    const int brow = tid >> 4, bcol = (tid & 15) * 8;  // B loader: 16 k x 128 cols
    const int tx = tid & 15, ty = tid >> 4;            // 16x16 compute threads

    A += (size_t)blockIdx.y * 128 * lda;
    B += (size_t)blockIdx.x * 128;
    C += (size_t)blockIdx.y * 128 * ldc + (size_t)blockIdx.x * 128;

    const float* Arow = A + (size_t)arow * lda + acol;
    const float* Brow0 = B + (size_t)brow * ldb + bcol;

    const int nT = K / 16;

    // staging registers
    float4 a0, a1, b0, b1;

    // prologue: chunk 0 -> stage 0
    a0 = *(const float4*)(Arow);
    a1 = *(const float4*)(Arow + 4);
    b0 = *(const float4*)(Brow0);
    b1 = *(const float4*)(Brow0 + 4);
    {
        As[0][acol + 0][arow] = a0.x; As[0][acol + 1][arow] = a0.y;
        As[0][acol + 2][arow] = a0.z; As[0][acol + 3][arow] = a0.w;
        As[0][acol + 4][arow] = a1.x; As[0][acol + 5][arow] = a1.y;
        As[0][acol + 6][arow] = a1.z; As[0][acol + 7][arow] = a1.w;
        *(float4*)&Bs[0][brow][bcol]     = b0;
        *(float4*)&Bs[0][brow][bcol + 4] = b1;
    }
    __syncthreads();

    float acc[8][8];
#pragma unroll
    for (int i = 0; i < 8; i++)
#pragma unroll
        for (int j = 0; j < 8; j++) acc[i][j] = 0.f;

    for (int t = 0; t < nT; t++) {
        // issue global loads for chunk t+1 (latency overlapped with compute)
        if (t + 1 < nT) {
            const float* An = Arow + (t + 1) * 16;
            const float* Bn = Brow0 + (size_t)(t + 1) * 16 * ldb;
            a0 = *(const float4*)(An);
            a1 = *(const float4*)(An + 4);
            b0 = *(const float4*)(Bn);
            b1 = *(const float4*)(Bn + 4);
        }

        const int s = t & 1;
#pragma unroll
        for (int k = 0; k < 16; k++) {
            float ar[8], br[8];
            *(float4*)&ar[0] = *(const float4*)&As[s][k][ty * 4];
            *(float4*)&ar[4] = *(const float4*)&As[s][k][64 + ty * 4];
            *(float4*)&br[0] = *(const float4*)&Bs[s][k][tx * 4];
            *(float4*)&br[4] = *(const float4*)&Bs[s][k][64 + tx * 4];
#pragma unroll
            for (int i = 0; i < 8; i++)
#pragma unroll
                for (int j = 0; j < 8; j++) acc[i][j] += ar[i] * br[j];
        }

        // store chunk t+1 into the idle stage
        if (t + 1 < nT) {
            const int sn = (t + 1) & 1;
            As[sn][acol + 0][arow] = a0.x; As[sn][acol + 1][arow] = a0.y;
            As[sn][acol + 2][arow] = a0.z; As[sn][acol + 3][arow] = a0.w;
            As[sn][acol + 4][arow] = a1.x; As[sn][acol + 5][arow] = a1.y;
            As[sn][acol + 6][arow] = a1.z; As[sn][acol + 7][arow] = a1.w;
            *(float4*)&Bs[sn][brow][bcol]     = b0;
            *(float4*)&Bs[sn][brow][bcol + 4] = b1;
        }
        __syncthreads();
    }

    // epilogue: rows ty*4+i (+64), col groups tx*4 (+64); float4 stores
#pragma unroll
    for (int ih = 0; ih < 2; ih++) {
#pragma unroll
        for (int i = 0; i < 4; i++) {
            int row = ih * 64 + ty * 4 + i;
            float* cr = C + (size_t)row * ldc;
#pragma unroll
            for (int jh = 0; jh < 2; jh++) {
                float4 v;
                v.x = acc[ih * 4 + i][jh * 4 + 0];
                v.y = acc[ih * 4 + i][jh * 4 + 1];
                v.z = acc[ih * 4 + i][jh * 4 + 2];
                v.w = acc[ih * 4 + i][jh * 4 + 3];
                if (RELU) {
                    v.x = fmaxf(v.x, 0.f); v.y = fmaxf(v.y, 0.f);
                    v.z = fmaxf(v.z, 0.f); v.w = fmaxf(v.w, 0.f);
                }
                *(float4*)(cr + jh * 64 + tx * 4) = v;
            }
        }
    }
}

// GEMM1: h[e] = relu(disp[e] @ wi[e]),  [G*C,768] @ [768,3072]
__global__ __launch_bounds__(256, 2) void gemm1_kernel(const float* __restrict__ wi, int G) {
    int e = blockIdx.z;
    const float* A = g_disp + (size_t)e * G * CAP * MDIM;
    const float* B = wi + (size_t)e * MDIM * HDIM;
    float* C = g_h + (size_t)e * G * CAP * HDIM;
    sgemm_body<true>(A, B, C, MDIM, MDIM, HDIM, HDIM);
}

// GEMM2: eo[e] = h[e] @ wo[e],  [G*C,3072] @ [3072,768]
__global__ __launch_bounds__(256, 2) void gemm2_kernel(const float* __restrict__ wo, int G) {
    int e = blockIdx.z;
    const float* A = g_h + (size_t)e * G * CAP * HDIM;
    const float* B = wo + (size_t)e * HDIM * MDIM;
    float* C = g_eo + (size_t)e * G * CAP * MDIM;
    sgemm_body<false>(A, B, C, HDIM, HDIM, MDIM, MDIM);
}

// ---------------- 6) combine ------------------------------------------------
__global__ void combine_kernel(float* __restrict__ out, int G) {
    int t = blockIdx.x;
    int g = t / SDIM;
    int p1 = g_pos1[t], p2 = g_pos2[t];
    float w1 = g_w1[t], w2 = g_w2[t];
    const float* r1 = (p1 >= 0) ? g_eo + (((size_t)g_e1[t] * G + g) * CAP + p1) * MDIM : nullptr;
    const float* r2 = (p2 >= 0) ? g_eo + (((size_t)g_e2[t] * G + g) * CAP + p2) * MDIM : nullptr;
    float* o = out + (size_t)t * MDIM;
    for (int m = threadIdx.x; m < MDIM; m += blockDim.x) {
        float v = 0.f;
        if (r1) v += w1 * r1[m];
        if (r2) v += w2 * r2[m];
        o[m] = v;
    }
}

// ---------------- launcher --------------------------------------------------
extern "C" void kernel_launch(void* const* d_in, const int* in_sizes, int n_in,
                              void* d_out, int out_size) {
    const float* x  = (const float*)d_in[0];   // [4,1024,768] fp32
    const float* wg = (const float*)d_in[1];   // [768,16]
    const float* wi = (const float*)d_in[2];   // [16,768,3072]
    const float* wo = (const float*)d_in[3];   // [16,3072,768]
    float* out = (float*)d_out;

    int T = in_sizes[0] / MDIM;   // 4096 tokens
    int G = T / SDIM;             // 2 groups
    if (G > GMAX) G = GMAX;
    int Mr = G * CAP;             // 512 rows per expert

    gating_kernel<<<(T + 3) / 4, 128>>>(x, wg, T);
    scan_kernel<<<G, 256>>>(G);
    scatter_kernel<<<T, 256>>>(x, G);
    gemm1_kernel<<<dim3(HDIM / 128, Mr / 128, NEXP), 256>>>(wi, G);
    gemm2_kernel<<<dim3(MDIM / 128, Mr / 128, NEXP), 256>>>(wo, G);
    combine_kernel<<<T, 256>>>(out, G);
}

// round 9
// speedup vs baseline: 1.3139x; 1.0533x over previous
#include <cuda_runtime.h>
#include <cuda_bf16.h>

// Problem constants (fixed by the dataset)
#define SDIM 2048   // tokens per group
#define MDIM 768    // hidden size
#define HDIM 3072   // intermediate size
#define NEXP 16     // num experts
#define CAP  256    // capacity = 2*S/E
#define GMAX 2      // groups (4*1024 tokens / 2048)
#define KSPLIT 4    // split-K factor for GEMM2 (3072/4 = 768 per slice)

// ---------------- scratch (device globals; no runtime allocation) -----------
__device__ __align__(128) float g_disp[NEXP * GMAX * CAP * MDIM];   // [E][G][C][M]
__device__ __align__(128) float g_h   [NEXP * GMAX * CAP * HDIM];   // [E][G][C][H]
__device__ __align__(128) float g_eoP [KSPLIT * NEXP * GMAX * CAP * MDIM]; // [S][E][G][C][M]
__device__ int   g_e1  [GMAX * SDIM];
__device__ int   g_e2  [GMAX * SDIM];
__device__ int   g_pos1[GMAX * SDIM];                // -1 => dropped
__device__ int   g_pos2[GMAX * SDIM];
__device__ float g_gv1 [GMAX * SDIM];
__device__ float g_gv2 [GMAX * SDIM];
__device__ float g_w1  [GMAX * SDIM];
__device__ float g_w2  [GMAX * SDIM];

// ---------------- 1) gating: softmax(x @ wg), top-2 -------------------------
__global__ void gating_kernel(const float* __restrict__ x,
                              const float* __restrict__ wg, int T) {
    int warp = (blockIdx.x * blockDim.x + threadIdx.x) >> 5;
    int lane = threadIdx.x & 31;
    if (warp >= T) return;
    const float* xr = x + (size_t)warp * MDIM;
    float acc[NEXP];
#pragma unroll
    for (int e = 0; e < NEXP; e++) acc[e] = 0.f;
    for (int k = lane; k < MDIM; k += 32) {
        float xv = xr[k];
        const float* w = wg + k * NEXP;
#pragma unroll
        for (int e = 0; e < NEXP; e++) acc[e] += xv * w[e];
    }
#pragma unroll
    for (int e = 0; e < NEXP; e++) {
#pragma unroll
        for (int off = 16; off; off >>= 1)
            acc[e] += __shfl_xor_sync(0xffffffffu, acc[e], off);
    }
    if (lane == 0) {
        float mx = acc[0];
#pragma unroll
        for (int e = 1; e < NEXP; e++) mx = fmaxf(mx, acc[e]);
        float p[NEXP], sum = 0.f;
#pragma unroll
        for (int e = 0; e < NEXP; e++) { p[e] = expf(acc[e] - mx); sum += p[e]; }
        float inv = 1.f / sum;
        int e1 = 0; float b1 = p[0];
#pragma unroll
        for (int e = 1; e < NEXP; e++) if (p[e] > b1) { b1 = p[e]; e1 = e; }
        int e2 = 0; float b2 = -1.f;
#pragma unroll
        for (int e = 0; e < NEXP; e++)
            if (e != e1 && p[e] > b2) { b2 = p[e]; e2 = e; }
        g_e1[warp] = e1; g_e2[warp] = e2;
        g_gv1[warp] = b1 * inv; g_gv2[warp] = b2 * inv;
    }
}

// ---------------- 2) capacity scan per group --------------------------------
__global__ void scan_kernel(int G) {
    int g = blockIdx.x;
    int tid = threadIdx.x;
    __shared__ int s_cnt1[NEXP];
    int base = g * SDIM;
    if (tid < NEXP) {
        int cnt = 0;
        for (int s = 0; s < SDIM; s++) {
            if (g_e1[base + s] == tid) {
                int p = cnt++;
                g_pos1[base + s] = (p < CAP) ? p : -1;
            }
        }
        s_cnt1[tid] = cnt < CAP ? cnt : CAP;
    }
    __syncthreads();
    if (tid < NEXP) {
        int cnt = 0, off = s_cnt1[tid];
        for (int s = 0; s < SDIM; s++) {
            if (g_e2[base + s] == tid) {
                int p = cnt++ + off;
                g_pos2[base + s] = (p < CAP) ? p : -1;
            }
        }
    }
    __syncthreads();
    for (int s = tid; s < SDIM; s += blockDim.x) {
        int t = base + s;
        float a = (g_pos1[t] >= 0) ? g_gv1[t] : 0.f;
        float b = (g_pos2[t] >= 0) ? g_gv2[t] : 0.f;
        float den = a + b;
        den = (den > 0.f) ? den : 1.f;
        g_w1[t] = a / den;
        g_w2[t] = b / den;
    }
}

// ---------------- 3) scatter tokens into dispatch buffer --------------------
__global__ void scatter_kernel(const float* __restrict__ x, int G) {
    int t = blockIdx.x;
    int g = t / SDIM;
    const float* xr = x + (size_t)t * MDIM;
    int p1 = g_pos1[t], p2 = g_pos2[t];
    float* d1 = (p1 >= 0) ? g_disp + (((size_t)g_e1[t] * G + g) * CAP + p1) * MDIM : nullptr;
    float* d2 = (p2 >= 0) ? g_disp + (((size_t)g_e2[t] * G + g) * CAP + p2) * MDIM : nullptr;
    for (int m = threadIdx.x; m < MDIM; m += blockDim.x) {
        float v = xr[m];
        if (d1) d1[m] = v;
        if (d2) d2[m] = v;
    }
}

// ---------------- 4/5) SGEMM body: 128x128 tile, K-chunk 16, double-buffered -
template<bool RELU>
__device__ __forceinline__ void sgemm_body(
    const float* __restrict__ A, const float* __restrict__ B, float* __restrict__ C,
    int K, int lda, int ldb, int ldc) {
    __shared__ float As[2][16][128];
    __shared__ float Bs[2][16][128];
    const int tid = threadIdx.x;
    const int arow = tid >> 1, acol = (tid & 1) * 8;   // A loader: 128 rows x 16 k
    const int brow = tid >> 4, bcol = (tid & 15) * 8;  // B loader: 16 k x 128 cols
    const int tx = tid & 15, ty = tid >> 4;            // 16x16 compute threads

    A += (size_t)blockIdx.y * 128 * lda;
    B += (size_t)blockIdx.x * 128;
    C += (size_t)blockIdx.y * 128 * ldc + (size_t)blockIdx.x * 128;

    const float* Arow = A + (size_t)arow * lda + acol;
    const float* Brow0 = B + (size_t)brow * ldb + bcol;

    const int nT = K / 16;

    float4 a0, a1, b0, b1;

    a0 = *(const float4*)(Arow);
    a1 = *(const float4*)(Arow + 4);
    b0 = *(const float4*)(Brow0);
    b1 = *(const float4*)(Brow0 + 4);
    {
        As[0][acol + 0][arow] = a0.x; As[0][acol + 1][arow] = a0.y;
        As[0][acol + 2][arow] = a0.z; As[0][acol + 3][arow] = a0.w;
        As[0][acol + 4][arow] = a1.x; As[0][acol + 5][arow] = a1.y;
        As[0][acol + 6][arow] = a1.z; As[0][acol + 7][arow] = a1.w;
        *(float4*)&Bs[0][brow][bcol]     = b0;
        *(float4*)&Bs[0][brow][bcol + 4] = b1;
    }
    __syncthreads();

    float acc[8][8];
#pragma unroll
    for (int i = 0; i < 8; i++)
#pragma unroll
        for (int j = 0; j < 8; j++) acc[i][j] = 0.f;

    for (int t = 0; t < nT; t++) {
        if (t + 1 < nT) {
            const float* An = Arow + (t + 1) * 16;
            const float* Bn = Brow0 + (size_t)(t + 1) * 16 * ldb;
            a0 = *(const float4*)(An);
            a1 = *(const float4*)(An + 4);
            b0 = *(const float4*)(Bn);
            b1 = *(const float4*)(Bn + 4);
        }

        const int s = t & 1;
#pragma unroll
        for (int k = 0; k < 16; k++) {
            float ar[8], br[8];
            *(float4*)&ar[0] = *(const float4*)&As[s][k][ty * 4];
            *(float4*)&ar[4] = *(const float4*)&As[s][k][64 + ty * 4];
            *(float4*)&br[0] = *(const float4*)&Bs[s][k][tx * 4];
            *(float4*)&br[4] = *(const float4*)&Bs[s][k][64 + tx * 4];
#pragma unroll
            for (int i = 0; i < 8; i++)
#pragma unroll
                for (int j = 0; j < 8; j++) acc[i][j] += ar[i] * br[j];
        }

        if (t + 1 < nT) {
            const int sn = (t + 1) & 1;
            As[sn][acol + 0][arow] = a0.x; As[sn][acol + 1][arow] = a0.y;
            As[sn][acol + 2][arow] = a0.z; As[sn][acol + 3][arow] = a0.w;
            As[sn][acol + 4][arow] = a1.x; As[sn][acol + 5][arow] = a1.y;
            As[sn][acol + 6][arow] = a1.z; As[sn][acol + 7][arow] = a1.w;
            *(float4*)&Bs[sn][brow][bcol]     = b0;
            *(float4*)&Bs[sn][brow][bcol + 4] = b1;
        }
        __syncthreads();
    }

#pragma unroll
    for (int ih = 0; ih < 2; ih++) {
#pragma unroll
        for (int i = 0; i < 4; i++) {
            int row = ih * 64 + ty * 4 + i;
            float* cr = C + (size_t)row * ldc;
#pragma unroll
            for (int jh = 0; jh < 2; jh++) {
                float4 v;
                v.x = acc[ih * 4 + i][jh * 4 + 0];
                v.y = acc[ih * 4 + i][jh * 4 + 1];
                v.z = acc[ih * 4 + i][jh * 4 + 2];
                v.w = acc[ih * 4 + i][jh * 4 + 3];
                if (RELU) {
                    v.x = fmaxf(v.x, 0.f); v.y = fmaxf(v.y, 0.f);
                    v.z = fmaxf(v.z, 0.f); v.w = fmaxf(v.w, 0.f);
                }
                *(float4*)(cr + jh * 64 + tx * 4) = v;
            }
        }
    }
}

// GEMM1: h[e] = relu(disp[e] @ wi[e]),  [G*C,768] @ [768,3072]
__global__ __launch_bounds__(256, 2) void gemm1_kernel(const float* __restrict__ wi, int G) {
    int e = blockIdx.z;
    const float* A = g_disp + (size_t)e * G * CAP * MDIM;
    const float* B = wi + (size_t)e * MDIM * HDIM;
    float* C = g_h + (size_t)e * G * CAP * HDIM;
    sgemm_body<true>(A, B, C, MDIM, MDIM, HDIM, HDIM);
}

// GEMM2 split-K: eoP[s][e] = h[e][:, sK:(s+1)K] @ wo[e][sK:(s+1)K, :]
// blockIdx.z encodes (slice, expert): z = s * NEXP + e
__global__ __launch_bounds__(256, 2) void gemm2_kernel(const float* __restrict__ wo, int G) {
    int z = blockIdx.z;
    int s = z / NEXP;
    int e = z - s * NEXP;
    const int KS = HDIM / KSPLIT;          // 768 per slice
    const float* A = g_h + (size_t)e * G * CAP * HDIM + (size_t)s * KS;
    const float* B = wo + (size_t)e * HDIM * MDIM + (size_t)s * KS * MDIM;
    float* C = g_eoP + ((size_t)s * NEXP + e) * G * CAP * MDIM;
    sgemm_body<false>(A, B, C, KS, HDIM, MDIM, MDIM);
}

// ---------------- 6) combine (sums split-K partials) -------------------------
__global__ void combine_kernel(float* __restrict__ out, int G) {
    int t = blockIdx.x;
    int g = t / SDIM;
    int p1 = g_pos1[t], p2 = g_pos2[t];
    float w1 = g_w1[t], w2 = g_w2[t];
    const size_t sliceStride = (size_t)NEXP * G * CAP * MDIM;
    const float* r1 = (p1 >= 0) ? g_eoP + (((size_t)g_e1[t] * G + g) * CAP + p1) * MDIM : nullptr;
    const float* r2 = (p2 >= 0) ? g_eoP + (((size_t)g_e2[t] * G + g) * CAP + p2) * MDIM : nullptr;
    float* o = out + (size_t)t * MDIM;
    for (int m = threadIdx.x; m < MDIM; m += blockDim.x) {
        float v = 0.f;
        if (r1) {
            float s1 = 0.f;
#pragma unroll
            for (int s = 0; s < KSPLIT; s++) s1 += r1[s * sliceStride + m];
            v += w1 * s1;
        }
        if (r2) {
            float s2 = 0.f;
#pragma unroll
            for (int s = 0; s < KSPLIT; s++) s2 += r2[s * sliceStride + m];
            v += w2 * s2;
        }
        o[m] = v;
    }
}

// ---------------- launcher --------------------------------------------------
extern "C" void kernel_launch(void* const* d_in, const int* in_sizes, int n_in,
                              void* d_out, int out_size) {
    const float* x  = (const float*)d_in[0];   // [4,1024,768] fp32
    const float* wg = (const float*)d_in[1];   // [768,16]
    const float* wi = (const float*)d_in[2];   // [16,768,3072]
    const float* wo = (const float*)d_in[3];   // [16,3072,768]
    float* out = (float*)d_out;

    int T = in_sizes[0] / MDIM;   // 4096 tokens
    int G = T / SDIM;             // 2 groups
    if (G > GMAX) G = GMAX;
    int Mr = G * CAP;             // 512 rows per expert

    gating_kernel<<<(T + 3) / 4, 128>>>(x, wg, T);
    scan_kernel<<<G, 256>>>(G);
    scatter_kernel<<<T, 256>>>(x, G);
    gemm1_kernel<<<dim3(HDIM / 128, Mr / 128, NEXP), 256>>>(wi, G);
    gemm2_kernel<<<dim3(MDIM / 128, Mr / 128, NEXP * KSPLIT), 256>>>(wo, G);
    combine_kernel<<<T, 256>>>(out, G);
}